// round 16
// baseline (speedup 1.0000x reference)
#include <cuda_runtime.h>

#define HH 256
#define WW 256
#define BB 2
#define CC 4
#define NROWS (BB*HH)        // 512 blocks, one per (b,h) row
#define NTOT (BB*CC*HH*WW)   // 524288
#define FPS 4096.0f
#define INV_FPS (1.0f/4096.0f)
#define FULLM 0xffffffffu

// Global accumulators (zero-init; finalize resets per replay)
__device__ int gA = 0;
__device__ int gS[2*CC] = {0,0,0,0,0,0,0,0};
__device__ int gM[2*CC] = {0,0,0,0,0,0,0,0};  // rare best>=2 reports

__device__ __forceinline__ int labAt(const int* __restrict__ y, int shift,
                                     int b, int idx) {
    return y[((b << 16) + idx) << shift];
}

__global__ void __launch_bounds__(256) rw_main(const int* __restrict__ y,
                                               const float* __restrict__ x) {
    __shared__ int sWA[8];               // per-warp A partials
    __shared__ int sWS[8][CC];           // per-warp S partials

    const int r    = blockIdx.x;         // b*256 + h
    const int b    = r >> 8;
    const int h    = r & 255;
    const int w    = threadIdx.x;        // column
    const int lane = w & 31;
    const int wid  = w >> 5;             // 0..7
    const int hw   = (h << 8) + w;

    // ---- x + sniff loads ----
    const float* xb = x + ((b * CC) << 16) + hw;
    float x0 = __ldg(xb);
    float x1 = __ldg(xb + (1 << 16));
    float x2 = __ldg(xb + (2 << 16));
    float x3 = __ldg(xb + (3 << 16));
    int  odd = __ldg(&y[2 * lane + 1]);  // int64 LE => all odd words zero

    const int is64  = __all_sync(FULLM, odd == 0);
    const int shift = is64 ? 1 : 0;

    // ---- own-column labels: rows h-1,h,h+1 clamped; one layout ----
    const int h0 = h > 0 ? h - 1 : 0;
    const int h2 = h < HH-1 ? h + 1 : HH-1;
    const int rs = WW << shift;
    const int o1 = (h - h0) * rs, o2 = (h2 - h0) * rs;
    const int* yb = y + ((((b << 16) + (h0 << 8)) + w) << shift);
    const int up = __ldg(yb);
    const int L  = __ldg(yb + o1);
    const int dn = __ldg(yb + o2);

    int eu = 0, em = 0, ed = 0;          // warp-edge adjacent column
    if (lane == 0 || lane == 31) {
        const int ec = (lane == 0) ? (w > 0 ? w - 1 : 0)
                                   : (w < WW-1 ? w + 1 : WW-1);
        const int* ye = y + ((((b << 16) + (h0 << 8)) + ec) << shift);
        eu = __ldg(ye);
        em = __ldg(ye + o1);
        ed = __ldg(ye + o2);
    }

    // ---- neighbor exchange via shuffles ----
    int u_l = __shfl_up_sync(FULLM, up, 1);
    int m_l = __shfl_up_sync(FULLM, L , 1);
    int d_l = __shfl_up_sync(FULLM, dn, 1);
    int u_r = __shfl_down_sync(FULLM, up, 1);
    int m_r = __shfl_down_sync(FULLM, L , 1);
    int d_r = __shfl_down_sync(FULLM, dn, 1);
    if (lane == 0)  { u_l = eu; m_l = em; d_l = ed; }
    if (lane == 31) { u_r = eu; m_r = em; d_r = ed; }

    // ---- d^2 to nearest differing label (integer-exact) ----
    int best;
    bool ax = (w > 0     && m_l != L) || (w < WW-1 && m_r != L) ||
              (h > 0     && up  != L) || (h < HH-1 && dn  != L);
    if (ax) {
        best = 1;
    } else {
        bool dg = false;
        if (h > 0) {
            if (w > 0    && u_l != L) dg = true;
            if (w < WW-1 && u_r != L) dg = true;
        }
        if (h < HH-1) {
            if (w > 0    && d_l != L) dg = true;
            if (w < WW-1 && d_r != L) dg = true;
        }
        best = dg ? 2 : 0x7fffffff;
        // Rare general rings (needs a 3x3 uniform patch: p ~ 4^-8)
        for (int R = 2; R < 512 && R * R < best; R++) {
            int hm = h - R, hp = h + R, wm = w - R, wp = w + R;
            int wlo = wm < 0 ? 0 : wm, whi = wp > WW-1 ? WW-1 : wp;
            if (hm >= 0)
                for (int ww = wlo; ww <= whi; ww++)
                    if (labAt(y, shift, b, hm * WW + ww) != L) {
                        int dw = ww - w, d2 = R*R + dw*dw;
                        if (d2 < best) best = d2;
                    }
            if (hp <= HH-1)
                for (int ww = wlo; ww <= whi; ww++)
                    if (labAt(y, shift, b, hp * WW + ww) != L) {
                        int dw = ww - w, d2 = R*R + dw*dw;
                        if (d2 < best) best = d2;
                    }
            int hlo = hm + 1 < 0 ? 0 : hm + 1;
            int hhi = hp - 1 > HH-1 ? HH-1 : hp - 1;
            if (wm >= 0)
                for (int hh = hlo; hh <= hhi; hh++)
                    if (labAt(y, shift, b, hh * WW + wm) != L) {
                        int dh = hh - h, d2 = R*R + dh*dh;
                        if (d2 < best) best = d2;
                    }
            if (wp <= WW-1)
                for (int hh = hlo; hh <= hhi; hh++)
                    if (labAt(y, shift, b, hh * WW + wp) != L) {
                        int dh = hh - h, d2 = R*R + dh*dh;
                        if (d2 < best) best = d2;
                    }
        }
    }

    // Rare M report (p ~ 0.4%): finalize applies the max(...,1) floor.
    if (best >= 2) atomicMax(&gM[b * CC + L], best);

    // ---- softmax p_L: exps relative to class 0 ----
    float e1 = __expf(x1 - x0);
    float e2 = __expf(x2 - x0);
    float e3 = __expf(x3 - x0);
    float eL = (L == 0) ? 1.0f : (L == 1) ? e1 : (L == 2) ? e2 : e3;
    float pL = eL * __frcp_rn(1.0f + e1 + e2 + e3);

    float sd = (best == 1) ? 1.0f
             : (best == 2) ? 1.41421356237f
             : sqrtf((float)best);

    // ---- fixed-point warp reduction (5 REDUX) -> smem slot (no atomics) ----
    int ai = __reduce_add_sync(FULLM, __float2int_rn((1.0f - pL) * FPS));
    int si = __float2int_rn(pL * sd * FPS);
    int wS[CC];
    #pragma unroll
    for (int c = 0; c < CC; c++)
        wS[c] = __reduce_add_sync(FULLM, (L == c) ? si : 0);

    if (lane == 0) {
        sWA[wid] = ai;
        #pragma unroll
        for (int c = 0; c < CC; c++) sWS[wid][c] = wS[c];
    }
    __syncthreads();                     // the only barrier

    // ---- warp 0 folds 8 slots; lanes 0-4 commit 5 parallel global adds ----
    if (w < 8) {
        int a = sWA[lane];
        int s0 = sWS[lane][0], s1 = sWS[lane][1];
        int s2 = sWS[lane][2], s3 = sWS[lane][3];
        a  = __reduce_add_sync(0xffu, a);
        s0 = __reduce_add_sync(0xffu, s0);
        s1 = __reduce_add_sync(0xffu, s1);
        s2 = __reduce_add_sync(0xffu, s2);
        s3 = __reduce_add_sync(0xffu, s3);
        if (lane == 0)      atomicAdd(&gA, a);
        else if (lane == 1) atomicAdd(&gS[b * CC + 0], s0);
        else if (lane == 2) atomicAdd(&gS[b * CC + 1], s1);
        else if (lane == 3) atomicAdd(&gS[b * CC + 2], s2);
        else if (lane == 4) atomicAdd(&gS[b * CC + 3], s3);
    }
    // No fence, no counter: PDL grid boundary publishes everything.
}

// Finalize: PDL-serialized; reads 17 values, emits scalar, resets for replay.
__global__ void rw_fin(float* __restrict__ out) {
#if __CUDA_ARCH__ >= 900
    cudaGridDependencySynchronize();
#endif
    if (threadIdx.x == 0) {
        float res = (float)gA * INV_FPS;
        gA = 0;
        #pragma unroll
        for (int k = 0; k < 2*CC; k++) {
            int Si = gS[k]; gS[k] = 0;
            int Mi = gM[k]; gM[k] = 0;
            float Mk = (float)(Mi > 1 ? Mi : 1);
            res -= ((float)Si * INV_FPS) / (sqrtf(Mk) + 1e-15f);
        }
        out[0] = res * (1.0f / (float)NTOT);
    }
}

// ---------------------------------------------------------------------------
extern "C" void kernel_launch(void* const* d_in, const int* in_sizes, int n_in,
                              void* d_out, int out_size) {
    const float* x;
    const void*  y;
    if (in_sizes[0] == NTOT) { x = (const float*)d_in[0]; y = d_in[1]; }
    else                     { x = (const float*)d_in[1]; y = d_in[0]; }
    float* out = (float*)d_out;

    rw_main<<<NROWS, 256>>>((const int*)y, x);

    cudaLaunchConfig_t cfg = {};
    cfg.gridDim  = dim3(1, 1, 1);
    cfg.blockDim = dim3(32, 1, 1);
    cudaLaunchAttribute attr[1];
    attr[0].id = cudaLaunchAttributeProgrammaticStreamSerialization;
    attr[0].val.programmaticStreamSerializationAllowed = 1;
    cfg.attrs    = attr;
    cfg.numAttrs = 1;
    cudaLaunchKernelEx(&cfg, rw_fin, out);
}

// round 17
// speedup vs baseline: 1.4669x; 1.4669x over previous
#include <cuda_runtime.h>

#define HH 256
#define WW 256
#define BB 2
#define CC 4
#define NROWS (BB*HH)        // 512 blocks, one per (b,h) row
#define NTOT (BB*CC*HH*WW)   // 524288
#define FPS 4096.0f
#define INV_FPS (1.0f/4096.0f)
#define FULLM 0xffffffffu

// Global integer accumulators (zero-init; finalize kernel resets per replay)
__device__ int gA = 0;
__device__ int gS[2*CC] = {0,0,0,0,0,0,0,0};
__device__ int gM[2*CC] = {0,0,0,0,0,0,0,0};

__device__ __forceinline__ int labAt(const int* __restrict__ y, int shift,
                                     int b, int idx) {
    return y[((b << 16) + idx) << shift];
}

__global__ void __launch_bounds__(256) rw_main(const int* __restrict__ y,
                                               const float* __restrict__ x) {
    __shared__ int sA, sS[CC], sM[CC];

    const int r    = blockIdx.x;         // b*256 + h
    const int b    = r >> 8;
    const int h    = r & 255;
    const int w    = threadIdx.x;        // column
    const int lane = w & 31;
    const int hw   = (h << 8) + w;

    // ---- x + sniff loads ----
    const float* xb = x + ((b * CC) << 16) + hw;
    float x0 = __ldg(xb);
    float x1 = __ldg(xb + (1 << 16));
    float x2 = __ldg(xb + (2 << 16));
    float x3 = __ldg(xb + (3 << 16));
    int  odd = __ldg(&y[2 * lane + 1]);  // int64 LE => all odd words zero

    if (w < CC)  { sS[w] = 0; sM[w] = 1; }   // sM floor = 1 (see M note)
    if (w == 32) sA = 0;
    __syncthreads();

    const int is64  = __all_sync(FULLM, odd == 0);
    const int shift = is64 ? 1 : 0;

    // ---- own-column labels: rows h-1,h,h+1 clamped; one layout ----
    const int h0 = h > 0 ? h - 1 : 0;
    const int h2 = h < HH-1 ? h + 1 : HH-1;
    const int rs = WW << shift;
    const int o1 = (h - h0) * rs, o2 = (h2 - h0) * rs;
    const int* yb = y + ((((b << 16) + (h0 << 8)) + w) << shift);
    const int up = __ldg(yb);
    const int L  = __ldg(yb + o1);
    const int dn = __ldg(yb + o2);

    int eu = 0, em = 0, ed = 0;          // warp-edge adjacent column
    if (lane == 0 || lane == 31) {
        const int ec = (lane == 0) ? (w > 0 ? w - 1 : 0)
                                   : (w < WW-1 ? w + 1 : WW-1);
        const int* ye = y + ((((b << 16) + (h0 << 8)) + ec) << shift);
        eu = __ldg(ye);
        em = __ldg(ye + o1);
        ed = __ldg(ye + o2);
    }

    // ---- neighbor exchange via shuffles ----
    int u_l = __shfl_up_sync(FULLM, up, 1);
    int m_l = __shfl_up_sync(FULLM, L , 1);
    int d_l = __shfl_up_sync(FULLM, dn, 1);
    int u_r = __shfl_down_sync(FULLM, up, 1);
    int m_r = __shfl_down_sync(FULLM, L , 1);
    int d_r = __shfl_down_sync(FULLM, dn, 1);
    if (lane == 0)  { u_l = eu; m_l = em; d_l = ed; }
    if (lane == 31) { u_r = eu; m_r = em; d_r = ed; }

    // ---- d^2 to nearest differing label (integer-exact) ----
    int best;
    bool ax = (w > 0     && m_l != L) || (w < WW-1 && m_r != L) ||
              (h > 0     && up  != L) || (h < HH-1 && dn  != L);
    if (ax) {
        best = 1;
    } else {
        bool dg = false;
        if (h > 0) {
            if (w > 0    && u_l != L) dg = true;
            if (w < WW-1 && u_r != L) dg = true;
        }
        if (h < HH-1) {
            if (w > 0    && d_l != L) dg = true;
            if (w < WW-1 && d_r != L) dg = true;
        }
        best = dg ? 2 : 0x7fffffff;
        // Rare general rings (needs a 3x3 uniform patch: p ~ 4^-8)
        for (int R = 2; R < 512 && R * R < best; R++) {
            int hm = h - R, hp = h + R, wm = w - R, wp = w + R;
            int wlo = wm < 0 ? 0 : wm, whi = wp > WW-1 ? WW-1 : wp;
            if (hm >= 0)
                for (int ww = wlo; ww <= whi; ww++)
                    if (labAt(y, shift, b, hm * WW + ww) != L) {
                        int dw = ww - w, d2 = R*R + dw*dw;
                        if (d2 < best) best = d2;
                    }
            if (hp <= HH-1)
                for (int ww = wlo; ww <= whi; ww++)
                    if (labAt(y, shift, b, hp * WW + ww) != L) {
                        int dw = ww - w, d2 = R*R + dw*dw;
                        if (d2 < best) best = d2;
                    }
            int hlo = hm + 1 < 0 ? 0 : hm + 1;
            int hhi = hp - 1 > HH-1 ? HH-1 : hp - 1;
            if (wm >= 0)
                for (int hh = hlo; hh <= hhi; hh++)
                    if (labAt(y, shift, b, hh * WW + wm) != L) {
                        int dh = hh - h, d2 = R*R + dh*dh;
                        if (d2 < best) best = d2;
                    }
            if (wp <= WW-1)
                for (int hh = hlo; hh <= hhi; hh++)
                    if (labAt(y, shift, b, hh * WW + wp) != L) {
                        int dh = hh - h, d2 = R*R + dh*dh;
                        if (d2 < best) best = d2;
                    }
        }
    }

    // M: per-block class max == max(1, reports from best>=2 lanes); absent
    // classes keep 1 but have S=0, so their term vanishes -> exact.
    if (best >= 2) atomicMax(&sM[L], best);

    // ---- softmax p_L: exps relative to class 0 ----
    float e1 = __expf(x1 - x0);
    float e2 = __expf(x2 - x0);
    float e3 = __expf(x3 - x0);
    float eL = (L == 0) ? 1.0f : (L == 1) ? e1 : (L == 2) ? e2 : e3;
    float pL = eL * __frcp_rn(1.0f + e1 + e2 + e3);

    float sd = (best == 1) ? 1.0f
             : (best == 2) ? 1.41421356237f
             : sqrtf((float)best);

    // ---- fixed-point warp reduction: 5 REDUX ----
    int ai = __reduce_add_sync(FULLM, __float2int_rn((1.0f - pL) * FPS));
    int si = __float2int_rn(pL * sd * FPS);
    int wS[CC];
    #pragma unroll
    for (int c = 0; c < CC; c++)
        wS[c] = __reduce_add_sync(FULLM, (L == c) ? si : 0);
    if (lane == 0) {
        atomicAdd(&sA, ai);
        #pragma unroll
        for (int c = 0; c < CC; c++)
            atomicAdd(&sS[c], wS[c]);
    }
    __syncthreads();

    // ---- commit block partials to global accumulators; then exit.
    // Visibility to the PDL-dependent finalize kernel is guaranteed at
    // grid completion (implicit trigger) -> no fence, no counter, no tail.
    if (w == 0)            atomicAdd(&gA, sA);
    else if (w < 1 + CC)   atomicAdd(&gS[b * CC + (w - 1)], sS[w - 1]);
    else if (w < 1 + 2*CC) atomicMax(&gM[b * CC + (w - 1 - CC)], sM[w - 1 - CC]);
}

// Finalize: launched with programmatic stream serialization; waits on the
// primary grid, reads 17 values, emits the scalar, resets for replay.
__global__ void rw_fin(float* __restrict__ out) {
#if __CUDA_ARCH__ >= 900
    cudaGridDependencySynchronize();
#endif
    if (threadIdx.x == 0) {
        float res = (float)gA * INV_FPS;
        #pragma unroll
        for (int k = 0; k < 2*CC; k++) {
            float Sk = (float)gS[k] * INV_FPS;
            float Mk = (float)gM[k];
            res -= Sk / (sqrtf(Mk) + 1e-15f);
        }
        out[0] = res * (1.0f / (float)NTOT);
        gA = 0;
        #pragma unroll
        for (int k = 0; k < 2*CC; k++) { gS[k] = 0; gM[k] = 0; }
    }
}

// ---------------------------------------------------------------------------
extern "C" void kernel_launch(void* const* d_in, const int* in_sizes, int n_in,
                              void* d_out, int out_size) {
    const float* x;
    const void*  y;
    if (in_sizes[0] == NTOT) { x = (const float*)d_in[0]; y = d_in[1]; }
    else                     { x = (const float*)d_in[1]; y = d_in[0]; }
    float* out = (float*)d_out;

    rw_main<<<NROWS, 256>>>((const int*)y, x);

    // PDL launch: overlaps this node's launch latency with rw_main execution.
    cudaLaunchConfig_t cfg = {};
    cfg.gridDim  = dim3(1, 1, 1);
    cfg.blockDim = dim3(32, 1, 1);
    cudaLaunchAttribute attr[1];
    attr[0].id = cudaLaunchAttributeProgrammaticStreamSerialization;
    attr[0].val.programmaticStreamSerializationAllowed = 1;
    cfg.attrs    = attr;
    cfg.numAttrs = 1;
    cudaLaunchKernelEx(&cfg, rw_fin, out);
}